// round 2
// baseline (speedup 1.0000x reference)
#include <cuda_runtime.h>
#include <math.h>

#define Bv 8
#define Cv 64
#define Hv 256
#define Wv 256
#define HWv 65536
#define PI_F 3.14159265358979323846f

// Scratch (device globals: allocation-free rule)
__device__ float2 g_dir[Bv * HWv];                  // (cos, sin) per pixel
__device__ float2 g_G2[(size_t)8 * Bv * HWv];       // [b][plane-pair 0..7][HW], .x/.y = 2 hidden ch
                                                    // pairs 0..3 = tan-proj h0..7, 4..7 = nor-proj h0..7

typedef unsigned long long u64;

// ---- packed f32x2 helpers (Blackwell) ----
__device__ __forceinline__ u64 ffma2(u64 a, u64 b, u64 c) {
    u64 d;
    asm("fma.rn.f32x2 %0, %1, %2, %3;" : "=l"(d) : "l"(a), "l"(b), "l"(c));
    return d;
}
__device__ __forceinline__ u64 pack2(float lo, float hi) {
    u64 u; asm("mov.b64 %0, {%1, %2};" : "=l"(u) : "f"(lo), "f"(hi)); return u;
}
__device__ __forceinline__ float2 unpack2(u64 u) {
    float2 v; asm("mov.b64 {%0, %1}, %2;" : "=f"(v.x), "=f"(v.y) : "l"(u)); return v;
}

// ============================================================
// K1: theta = pi*sigmoid(w1 . relu(conv3x3(x, w3)+b3) + b1) -> (cos, sin)
// thread = 4 vertical pixels; weights register-blocked from SMEM
// ============================================================
__global__ __launch_bounds__(128) void k_theta(
    const float* __restrict__ x, const float* __restrict__ w3,
    const float* __restrict__ b3, const float* __restrict__ w1,
    const float* __restrict__ b1)
{
    __shared__ float sw[Cv * 72];   // [c][tap][h]
    int tid = threadIdx.y * 32 + threadIdx.x;
    for (int i = tid; i < Cv * 72; i += 128) {
        int c = i / 72, r = i % 72, tap = r >> 3, h = r & 7;
        sw[i] = w3[(h * Cv + c) * 9 + tap];
    }
    __syncthreads();

    int xc = blockIdx.x * 32 + threadIdx.x;
    int y0 = blockIdx.y * 16 + threadIdx.y * 4;
    int b  = blockIdx.z;

    float acc[4][8];
    #pragma unroll
    for (int p = 0; p < 4; p++)
        #pragma unroll
        for (int h = 0; h < 8; h++) acc[p][h] = 0.f;

    const float* xb = x + (size_t)b * Cv * HWv;
    for (int c = 0; c < Cv; c++) {
        const float* xp = xb + c * HWv;
        float xv[6][3];
        #pragma unroll
        for (int r = 0; r < 6; r++) {
            int yy = y0 - 1 + r;
            bool yok = ((unsigned)yy < (unsigned)Hv);
            #pragma unroll
            for (int cc = 0; cc < 3; cc++) {
                int xx = xc - 1 + cc;
                xv[r][cc] = (yok && (unsigned)xx < (unsigned)Wv)
                          ? __ldg(xp + yy * Wv + xx) : 0.f;
            }
        }
        #pragma unroll
        for (int ky = 0; ky < 3; ky++)
        #pragma unroll
        for (int kx = 0; kx < 3; kx++) {
            const float* wp = &sw[c * 72 + (ky * 3 + kx) * 8];
            float wreg[8];
            #pragma unroll
            for (int h = 0; h < 8; h++) wreg[h] = wp[h];
            #pragma unroll
            for (int p = 0; p < 4; p++) {
                float v = xv[p + ky][kx];
                #pragma unroll
                for (int h = 0; h < 8; h++) acc[p][h] += v * wreg[h];
            }
        }
    }

    float w1r[8], b3r[8];
    #pragma unroll
    for (int h = 0; h < 8; h++) { w1r[h] = __ldg(w1 + h); b3r[h] = __ldg(b3 + h); }
    float bias1 = __ldg(b1);
    #pragma unroll
    for (int p = 0; p < 4; p++) {
        float z = bias1;
        #pragma unroll
        for (int h = 0; h < 8; h++) z += w1r[h] * fmaxf(acc[p][h] + b3r[h], 0.f);
        float theta = PI_F / (1.f + expf(-z));
        float s, cth; sincosf(theta, &s, &cth);
        g_dir[(size_t)b * HWv + (size_t)(y0 + p) * Wv + xc] = make_float2(cth, s);
    }
}

// ============================================================
// K2: G = wr-projection of x: 64 -> 16 channels, stored as 8 float2 planes
// thread = 2 vertical pixels
// ============================================================
__global__ __launch_bounds__(256) void k_proj(
    const float* __restrict__ x, const float* __restrict__ wr)
{
    __shared__ float swr[Cv * 16];  // [c][j]: j<8 tan (wr[j][c]), j>=8 nor (wr[j-8][64+c])
    int tid = threadIdx.x;
    for (int i = tid; i < Cv * 16; i += 256) {
        int c = i >> 4, j = i & 15;
        swr[i] = (j < 8) ? wr[j * 128 + c] : wr[(j - 8) * 128 + 64 + c];
    }
    __syncthreads();

    int g = blockIdx.x * 256 + tid;
    int xc = g % Wv;
    int yp = (g / Wv) % (Hv / 2);
    int b  = g / (Wv * (Hv / 2));
    int y0 = yp * 2;

    float acc0[16], acc1[16];
    #pragma unroll
    for (int j = 0; j < 16; j++) { acc0[j] = 0.f; acc1[j] = 0.f; }

    const float* xb = x + (size_t)b * Cv * HWv + (size_t)y0 * Wv + xc;
    for (int c = 0; c < Cv; c++) {
        float v0 = __ldg(xb + (size_t)c * HWv);
        float v1 = __ldg(xb + (size_t)c * HWv + Wv);
        #pragma unroll
        for (int j = 0; j < 16; j++) {
            float w = swr[c * 16 + j];
            acc0[j] += v0 * w;
            acc1[j] += v1 * w;
        }
    }
    size_t pb = (size_t)b * 8 * HWv + (size_t)y0 * Wv + xc;
    #pragma unroll
    for (int jp = 0; jp < 8; jp++) {
        g_G2[pb + (size_t)jp * HWv]      = make_float2(acc0[2*jp], acc0[2*jp+1]);
        g_G2[pb + (size_t)jp * HWv + Wv] = make_float2(acc1[2*jp], acc1[2*jp+1]);
    }
}

// ============================================================
// K3: oriented pooling on G (18 taps x 4 corners x 4 plane-pairs),
//     hidden -> relu -> we (8->128, packed over (c, c+64)) -> sigmoid -> gate x
// ============================================================
__device__ __forceinline__ void sample4(const float2* __restrict__ G,
                                        float cy, float cx, u64* hid)
{
    cy = fminf(fmaxf(cy, 0.f), (float)(Hv - 1));
    cx = fminf(fmaxf(cx, 0.f), (float)(Wv - 1));
    float y0f = floorf(cy), x0f = floorf(cx);
    float fy = cy - y0f, fx = cx - x0f;
    int iy0 = (int)y0f, ix0 = (int)x0f;
    int iy1 = min(iy0 + 1, Hv - 1), ix1 = min(ix0 + 1, Wv - 1);
    int o00 = iy0 * Wv + ix0, o01 = iy0 * Wv + ix1;
    int o10 = iy1 * Wv + ix0, o11 = iy1 * Wv + ix1;
    float w11 = fy * fx;
    float w10 = fy - w11, w01 = fx - w11, w00 = 1.f - fy - fx + w11;
    u64 W00 = pack2(w00, w00), W01 = pack2(w01, w01);
    u64 W10 = pack2(w10, w10), W11 = pack2(w11, w11);
    #pragma unroll
    for (int hp = 0; hp < 4; hp++) {
        const u64* pl = reinterpret_cast<const u64*>(G + (size_t)hp * HWv);
        hid[hp] = ffma2(__ldg(pl + o00), W00, hid[hp]);
        hid[hp] = ffma2(__ldg(pl + o01), W01, hid[hp]);
        hid[hp] = ffma2(__ldg(pl + o10), W10, hid[hp]);
        hid[hp] = ffma2(__ldg(pl + o11), W11, hid[hp]);
    }
}

__global__ __launch_bounds__(256) void k_pool(
    const float* __restrict__ x, const float* __restrict__ br,
    const float* __restrict__ we, const float* __restrict__ be,
    float* __restrict__ out)
{
    __shared__ u64 swe[512];   // [c][h] = {we[c][h], we[c+64][h]}
    __shared__ u64 sbe[64];    // {be[c], be[c+64]}
    __shared__ float sbr[8];
    int tid = threadIdx.x;
    for (int i = tid; i < 512; i += 256) {
        int c = i >> 3, h = i & 7;
        swe[i] = pack2(we[c * 8 + h], we[(c + 64) * 8 + h]);
    }
    if (tid < 64) sbe[tid] = pack2(be[tid], be[tid + 64]);
    if (tid < 8)  sbr[tid] = br[tid];
    __syncthreads();

    int g = blockIdx.x * 256 + tid;
    int pix = g % HWv;
    int b   = g / HWv;
    int px = pix % Wv, py = pix / Wv;
    float2 dir = g_dir[g];
    float cs = dir.x, sn = dir.y;
    float fpx = (float)px, fpy = (float)py;

    u64 hid2[8];
    #pragma unroll
    for (int i = 0; i < 8; i++) hid2[i] = 0ull;

    const float2* Gt = g_G2 + (size_t)b * 8 * HWv;
    const float2* Gn = Gt + (size_t)4 * HWv;
    #pragma unroll
    for (int ti = 0; ti < 9; ti++) {
        float t = (float)(ti - 4);
        sample4(Gt, fpy + t * sn, fpx + t * cs, hid2);       // tangential taps
        sample4(Gn, fpy + t * cs, fpx - t * sn, hid2 + 4);   // normal taps
    }

    float hid[8];
    #pragma unroll
    for (int h = 0; h < 8; h++) {
        float2 a  = unpack2(hid2[h >> 1]);
        float2 bn = unpack2(hid2[4 + (h >> 1)]);
        float vt = (h & 1) ? a.y : a.x;
        float vn = (h & 1) ? bn.y : bn.x;
        hid[h] = fmaxf((vt + vn) * (1.f / 9.f) + sbr[h], 0.f);
    }
    u64 hdup[8];
    #pragma unroll
    for (int h = 0; h < 8; h++) hdup[h] = pack2(hid[h], hid[h]);

    size_t base = (size_t)b * Cv * HWv + pix;
    for (int c = 0; c < Cv; c++) {
        u64 z = sbe[c];
        #pragma unroll
        for (int h = 0; h < 8; h++) z = ffma2(hdup[h], swe[c * 8 + h], z);
        float2 zf = unpack2(z);
        float alpha = 1.f / (1.f + __expf(-zf.x)) + 1.f / (1.f + __expf(-zf.y));
        size_t o = base + (size_t)c * HWv;
        out[o] = alpha * __ldg(x + o);
    }
}

// ============================================================
extern "C" void kernel_launch(void* const* d_in, const int* in_sizes, int n_in,
                              void* d_out, int out_size)
{
    const float* x  = (const float*)d_in[0];
    const float* w3 = (const float*)d_in[1];
    const float* b3 = (const float*)d_in[2];
    const float* w1 = (const float*)d_in[3];
    const float* b1 = (const float*)d_in[4];
    const float* wr = (const float*)d_in[5];
    const float* br = (const float*)d_in[6];
    const float* we = (const float*)d_in[7];
    const float* be = (const float*)d_in[8];
    float* out = (float*)d_out;

    dim3 gb1(Wv / 32, Hv / 16, Bv), tb1(32, 4);
    k_theta<<<gb1, tb1>>>(x, w3, b3, w1, b1);
    k_proj<<<(Bv * HWv / 2) / 256, 256>>>(x, wr);
    k_pool<<<(Bv * HWv) / 256, 256>>>(x, br, we, be, out);
}

// round 3
// speedup vs baseline: 1.2779x; 1.2779x over previous
#include <cuda_runtime.h>
#include <math.h>

#define Bv 8
#define Cv 64
#define Hv 256
#define Wv 256
#define HWv 65536
#define BHW (Bv * HWv)
#define PI_F 3.14159265358979323846f

typedef unsigned long long u64;

// Scratch (device globals: allocation-free rule)
__device__ float2 g_dir[BHW];                    // (cos, sin) per pixel
__device__ float2 g_G2[(size_t)8 * BHW];         // 8 plane-pairs: 0..3 tan-proj h0..7, 4..7 nor-proj
__device__ float  g_hid[(size_t)8 * BHW];        // relu'd hidden, plane-per-h layout

// ---- packed f32x2 helpers (Blackwell) ----
__device__ __forceinline__ u64 ffma2(u64 a, u64 b, u64 c) {
    u64 d;
    asm("fma.rn.f32x2 %0, %1, %2, %3;" : "=l"(d) : "l"(a), "l"(b), "l"(c));
    return d;
}
__device__ __forceinline__ u64 pack2(float lo, float hi) {
    u64 u; asm("mov.b64 %0, {%1, %2};" : "=l"(u) : "f"(lo), "f"(hi)); return u;
}
__device__ __forceinline__ float2 unpack2(u64 u) {
    float2 v; asm("mov.b64 {%0, %1}, %2;" : "=f"(v.x), "=f"(v.y) : "l"(u)); return v;
}
__device__ __forceinline__ float fsig(float z) {          // fast sigmoid
    return __fdividef(1.f, 1.f + __expf(-z));
}

// ============================================================
// K1: theta = pi*sigmoid(w1 . relu(conv3x3(x,w3)+b3) + b1) -> (cos,sin)
// thread = 4 vertical pixels; hidden-channel pairs packed in f32x2
// ============================================================
__global__ __launch_bounds__(128) void k_theta(
    const float* __restrict__ x, const float* __restrict__ w3,
    const float* __restrict__ b3, const float* __restrict__ w1,
    const float* __restrict__ b1)
{
    // [c][tap][hp]: u64 = (w3[2hp][c][tap], w3[2hp+1][c][tap])
    __shared__ __align__(16) u64 sw2[Cv * 36];
    int tid = threadIdx.y * 32 + threadIdx.x;
    for (int i = tid; i < Cv * 36; i += 128) {
        int c = i / 36, r = i % 36, tap = r >> 2, hp = r & 3;
        sw2[i] = pack2(w3[((2 * hp) * Cv + c) * 9 + tap],
                       w3[((2 * hp + 1) * Cv + c) * 9 + tap]);
    }
    __syncthreads();

    int xc = blockIdx.x * 32 + threadIdx.x;
    int y0 = blockIdx.y * 16 + threadIdx.y * 4;
    int b  = blockIdx.z;

    u64 acc2[4][4];
    #pragma unroll
    for (int p = 0; p < 4; p++)
        #pragma unroll
        for (int hp = 0; hp < 4; hp++) acc2[p][hp] = 0ull;

    const float* xb = x + (size_t)b * Cv * HWv;
    for (int c = 0; c < Cv; c++) {
        const float* xp = xb + c * HWv;
        float xv[6][3];
        #pragma unroll
        for (int r = 0; r < 6; r++) {
            int yy = y0 - 1 + r;
            bool yok = ((unsigned)yy < (unsigned)Hv);
            #pragma unroll
            for (int cc = 0; cc < 3; cc++) {
                int xx = xc - 1 + cc;
                xv[r][cc] = (yok && (unsigned)xx < (unsigned)Wv)
                          ? __ldg(xp + yy * Wv + xx) : 0.f;
            }
        }
        const u64* wc = sw2 + c * 36;
        #pragma unroll
        for (int ky = 0; ky < 3; ky++)
        #pragma unroll
        for (int kx = 0; kx < 3; kx++) {
            int tap = ky * 3 + kx;
            ulonglong2 wA = *reinterpret_cast<const ulonglong2*>(wc + tap * 4);
            ulonglong2 wB = *reinterpret_cast<const ulonglong2*>(wc + tap * 4 + 2);
            #pragma unroll
            for (int p = 0; p < 4; p++) {
                float v = xv[p + ky][kx];
                u64 vd = pack2(v, v);
                acc2[p][0] = ffma2(vd, wA.x, acc2[p][0]);
                acc2[p][1] = ffma2(vd, wA.y, acc2[p][1]);
                acc2[p][2] = ffma2(vd, wB.x, acc2[p][2]);
                acc2[p][3] = ffma2(vd, wB.y, acc2[p][3]);
            }
        }
    }

    float w1r[8], b3r[8];
    #pragma unroll
    for (int h = 0; h < 8; h++) { w1r[h] = __ldg(w1 + h); b3r[h] = __ldg(b3 + h); }
    float bias1 = __ldg(b1);
    #pragma unroll
    for (int p = 0; p < 4; p++) {
        float z = bias1;
        #pragma unroll
        for (int hp = 0; hp < 4; hp++) {
            float2 a = unpack2(acc2[p][hp]);
            z += w1r[2 * hp]     * fmaxf(a.x + b3r[2 * hp], 0.f);
            z += w1r[2 * hp + 1] * fmaxf(a.y + b3r[2 * hp + 1], 0.f);
        }
        float theta = PI_F * fsig(z);
        float s, cth; __sincosf(theta, &s, &cth);
        g_dir[(size_t)b * HWv + (size_t)(y0 + p) * Wv + xc] = make_float2(cth, s);
    }
}

// ============================================================
// K2: G = wr-projection of x: 64 -> 16 ch, stored as 8 float2 planes.
// thread = 2 vertical pixels packed in f32x2
// ============================================================
__global__ __launch_bounds__(256) void k_proj(
    const float* __restrict__ x, const float* __restrict__ wr)
{
    // [c][j] dup pairs: j<8 tan (wr[j][c]), j>=8 nor (wr[j-8][64+c])
    __shared__ __align__(16) u64 swr2[Cv * 16];
    int tid = threadIdx.x;
    for (int i = tid; i < Cv * 16; i += 256) {
        int c = i >> 4, j = i & 15;
        float w = (j < 8) ? wr[j * 128 + c] : wr[(j - 8) * 128 + 64 + c];
        swr2[i] = pack2(w, w);
    }
    __syncthreads();

    int g = blockIdx.x * 256 + tid;
    int xc = g % Wv;
    int yp = (g / Wv) % (Hv / 2);
    int b  = g / (Wv * (Hv / 2));
    int y0 = yp * 2;

    u64 acc2[16];   // (pix0, pix1) per projected channel j
    #pragma unroll
    for (int j = 0; j < 16; j++) acc2[j] = 0ull;

    const float* xb = x + (size_t)b * Cv * HWv + (size_t)y0 * Wv + xc;
    for (int c = 0; c < Cv; c++) {
        float v0 = __ldg(xb + (size_t)c * HWv);
        float v1 = __ldg(xb + (size_t)c * HWv + Wv);
        u64 vp = pack2(v0, v1);
        const ulonglong2* wq = reinterpret_cast<const ulonglong2*>(swr2 + c * 16);
        #pragma unroll
        for (int q = 0; q < 8; q++) {
            ulonglong2 w = wq[q];
            acc2[2 * q]     = ffma2(vp, w.x, acc2[2 * q]);
            acc2[2 * q + 1] = ffma2(vp, w.y, acc2[2 * q + 1]);
        }
    }
    size_t pb = (size_t)b * 8 * HWv + (size_t)y0 * Wv + xc;
    #pragma unroll
    for (int jp = 0; jp < 8; jp++) {
        float2 a = unpack2(acc2[2 * jp]);
        float2 c2 = unpack2(acc2[2 * jp + 1]);
        g_G2[pb + (size_t)jp * HWv]      = make_float2(a.x, c2.x);
        g_G2[pb + (size_t)jp * HWv + Wv] = make_float2(a.y, c2.y);
    }
}

// ============================================================
// K3: oriented pooling on G (18 taps x 4 corners x 4 plane-pairs)
//     -> relu'd hidden written to plane-major scratch
// ============================================================
__device__ __forceinline__ void sample4(const float2* __restrict__ G,
                                        float cy, float cx, u64* hid)
{
    cy = fminf(fmaxf(cy, 0.f), (float)(Hv - 1));
    cx = fminf(fmaxf(cx, 0.f), (float)(Wv - 1));
    float y0f = floorf(cy), x0f = floorf(cx);
    float fy = cy - y0f, fx = cx - x0f;
    int iy0 = (int)y0f, ix0 = (int)x0f;
    int iy1 = min(iy0 + 1, Hv - 1), ix1 = min(ix0 + 1, Wv - 1);
    int o00 = iy0 * Wv + ix0, o01 = iy0 * Wv + ix1;
    int o10 = iy1 * Wv + ix0, o11 = iy1 * Wv + ix1;
    float w11 = fy * fx;
    float w10 = fy - w11, w01 = fx - w11, w00 = 1.f - fy - fx + w11;
    u64 W00 = pack2(w00, w00), W01 = pack2(w01, w01);
    u64 W10 = pack2(w10, w10), W11 = pack2(w11, w11);
    #pragma unroll
    for (int hp = 0; hp < 4; hp++) {
        const u64* pl = reinterpret_cast<const u64*>(G + (size_t)hp * HWv);
        hid[hp] = ffma2(__ldg(pl + o00), W00, hid[hp]);
        hid[hp] = ffma2(__ldg(pl + o01), W01, hid[hp]);
        hid[hp] = ffma2(__ldg(pl + o10), W10, hid[hp]);
        hid[hp] = ffma2(__ldg(pl + o11), W11, hid[hp]);
    }
}

__global__ __launch_bounds__(256) void k_pool(const float* __restrict__ br)
{
    __shared__ float sbr[8];
    int tid = threadIdx.x;
    if (tid < 8) sbr[tid] = br[tid];
    __syncthreads();

    int g = blockIdx.x * 256 + tid;
    int pix = g % HWv;
    int b   = g / HWv;
    int px = pix % Wv, py = pix / Wv;
    float2 dir = g_dir[g];
    float cs = dir.x, sn = dir.y;
    float fpx = (float)px, fpy = (float)py;

    u64 hid2[8];
    #pragma unroll
    for (int i = 0; i < 8; i++) hid2[i] = 0ull;

    const float2* Gt = g_G2 + (size_t)b * 8 * HWv;
    const float2* Gn = Gt + (size_t)4 * HWv;
    #pragma unroll
    for (int ti = 0; ti < 9; ti++) {
        float t = (float)(ti - 4);
        sample4(Gt, fpy + t * sn, fpx + t * cs, hid2);       // tangential
        sample4(Gn, fpy + t * cs, fpx - t * sn, hid2 + 4);   // normal
    }

    #pragma unroll
    for (int h = 0; h < 8; h++) {
        float2 a  = unpack2(hid2[h >> 1]);
        float2 bn = unpack2(hid2[4 + (h >> 1)]);
        float vt = (h & 1) ? a.y : a.x;
        float vn = (h & 1) ? bn.y : bn.x;
        g_hid[(size_t)h * BHW + g] =
            fmaxf((vt + vn) * (1.f / 9.f) + sbr[h], 0.f);
    }
}

// ============================================================
// K4: gating — hidden -> we (8->128 packed over (c, c+64)) -> sigmoid
//     -> alpha * x.  thread = 4 horizontal pixels (float4 paths)
// ============================================================
__global__ __launch_bounds__(256) void k_gate(
    const float* __restrict__ x, const float* __restrict__ we,
    const float* __restrict__ be, float* __restrict__ out)
{
    __shared__ __align__(16) u64 swe[512];   // [c][h] = {we[c][h], we[c+64][h]}
    __shared__ u64 sbe[64];
    int tid = threadIdx.x;
    for (int i = tid; i < 512; i += 256) {
        int c = i >> 3, h = i & 7;
        swe[i] = pack2(we[c * 8 + h], we[(c + 64) * 8 + h]);
    }
    if (tid < 64) sbe[tid] = pack2(be[tid], be[tid + 64]);
    __syncthreads();

    int g = blockIdx.x * 256 + tid;          // pixel-quad index
    size_t p0 = (size_t)g * 4;               // global pixel base
    int b = g / (HWv / 4);

    u64 hdup[4][8];
    #pragma unroll
    for (int h = 0; h < 8; h++) {
        float4 hv = *reinterpret_cast<const float4*>(g_hid + (size_t)h * BHW + p0);
        hdup[0][h] = pack2(hv.x, hv.x);
        hdup[1][h] = pack2(hv.y, hv.y);
        hdup[2][h] = pack2(hv.z, hv.z);
        hdup[3][h] = pack2(hv.w, hv.w);
    }

    size_t pix_in_b = p0 - (size_t)b * HWv;
    size_t base = (size_t)b * Cv * HWv + pix_in_b;

    for (int c = 0; c < Cv; c++) {
        const ulonglong2* wq = reinterpret_cast<const ulonglong2*>(swe + c * 8);
        ulonglong2 wa = wq[0], wb = wq[1], wc2 = wq[2], wd = wq[3];
        u64 w[8] = {wa.x, wa.y, wb.x, wb.y, wc2.x, wc2.y, wd.x, wd.y};
        u64 bias = sbe[c];
        u64 z[4] = {bias, bias, bias, bias};
        #pragma unroll
        for (int h = 0; h < 8; h++) {
            #pragma unroll
            for (int p = 0; p < 4; p++)
                z[p] = ffma2(hdup[p][h], w[h], z[p]);
        }
        float4 xv = *reinterpret_cast<const float4*>(x + base + (size_t)c * HWv);
        float alpha[4];
        #pragma unroll
        for (int p = 0; p < 4; p++) {
            float2 zf = unpack2(z[p]);
            alpha[p] = fsig(zf.x) + fsig(zf.y);
        }
        float4 o = make_float4(alpha[0] * xv.x, alpha[1] * xv.y,
                               alpha[2] * xv.z, alpha[3] * xv.w);
        *reinterpret_cast<float4*>(out + base + (size_t)c * HWv) = o;
    }
}

// ============================================================
extern "C" void kernel_launch(void* const* d_in, const int* in_sizes, int n_in,
                              void* d_out, int out_size)
{
    const float* x  = (const float*)d_in[0];
    const float* w3 = (const float*)d_in[1];
    const float* b3 = (const float*)d_in[2];
    const float* w1 = (const float*)d_in[3];
    const float* b1 = (const float*)d_in[4];
    const float* wr = (const float*)d_in[5];
    const float* br = (const float*)d_in[6];
    const float* we = (const float*)d_in[7];
    const float* be = (const float*)d_in[8];
    float* out = (float*)d_out;

    dim3 gb1(Wv / 32, Hv / 16, Bv), tb1(32, 4);
    k_theta<<<gb1, tb1>>>(x, w3, b3, w1, b1);
    k_proj<<<(BHW / 2) / 256, 256>>>(x, wr);
    k_pool<<<BHW / 256, 256>>>(br);
    k_gate<<<(BHW / 4) / 256, 256>>>(x, we, be, out);
}